// round 8
// baseline (speedup 1.0000x reference)
#include <cuda_runtime.h>
#include <cuda_bf16.h>
#include <mma.h>
#include <cstdint>

using namespace nvcuda;

#define NN 50000
#define EE 800000
#define ET (EE + NN)
#define HEADS 4
#define HID 64
#define C1 256   /* HEADS*HID */
#define C2 64
#define NEG 0.2f

// ---------------- scratch (device globals; no cudaMalloc allowed) -------------
__device__ __align__(16) float g_h1[(size_t)NN * C1];
__device__ __align__(16) float g_als1[NN * HEADS];
__device__ __align__(16) float g_ald1[NN * HEADS];
__device__ __align__(16) float g_h2lin[(size_t)NN * C2];
__device__ float g_als2[NN];
__device__ float g_ald2[NN];
__device__ int   g_cnt[NN];
__device__ int   g_off[NN + 1];
__device__ int   g_cur[NN];
__device__ int   g_psrc[ET];
__device__ int   g_bsum[256];
__device__ __align__(16) __nv_bfloat16 g_xhi[(size_t)NN * 128];
__device__ __align__(16) __nv_bfloat16 g_xlo[(size_t)NN * 128];
__device__ __align__(16) __nv_bfloat16 g_h2hi[(size_t)NN * C1];
__device__ __align__(16) __nv_bfloat16 g_h2lo[(size_t)NN * C1];
__device__ __align__(16) __nv_bfloat16 g_w1hi[128 * C1];   // [k=128][n=256]
__device__ __align__(16) __nv_bfloat16 g_w1lo[128 * C1];
__device__ __align__(16) __nv_bfloat16 g_w2hi[C1 * C2];    // [k=256][n=64]
__device__ __align__(16) __nv_bfloat16 g_w2lo[C1 * C2];

__device__ __forceinline__ float lrelu(float x) { return x > 0.f ? x : NEG * x; }
__device__ __forceinline__ float elu_f(float x) { return x > 0.f ? x : __expf(x) - 1.f; }

__device__ __forceinline__ void cp16z(uint32_t d, const void* s, bool pred) {
  if (pred)
    asm volatile("cp.async.ca.shared.global [%0], [%1], 16;" :: "r"(d), "l"(s));
  else
    asm volatile("cp.async.ca.shared.global [%0], [%1], 16, 0;" :: "r"(d), "l"(s));
}
__device__ __forceinline__ void cpa_commit() {
  asm volatile("cp.async.commit_group;" ::: "memory");
}
template <int N>
__device__ __forceinline__ void cpa_wait() {
  asm volatile("cp.async.wait_group %0;" :: "n"(N) : "memory");
}

// ---------------- CSR build ---------------------------------------------------
__global__ void k_hist(const int* __restrict__ ei) {
  int e = blockIdx.x * blockDim.x + threadIdx.x;
  if (e < EE) atomicAdd(&g_cnt[ei[EE + e]], 1);
}

__global__ __launch_bounds__(256) void k_scan1() {
  int i = blockIdx.x * 256 + threadIdx.x;
  int v = 0;
  if (i < NN) { v = g_cnt[i] + 1; g_cnt[i] = 0; }
  int lane = threadIdx.x & 31, wid = threadIdx.x >> 5;
  int x = v;
#pragma unroll
  for (int o = 1; o < 32; o <<= 1) {
    int y = __shfl_up_sync(0xffffffffu, x, o);
    if (lane >= o) x += y;
  }
  __shared__ int ws[8];
  if (lane == 31) ws[wid] = x;
  __syncthreads();
  if (threadIdx.x < 8) {
    int z = ws[threadIdx.x];
#pragma unroll
    for (int o = 1; o < 8; o <<= 1) {
      int q = __shfl_up_sync(0xffu, z, o);
      if ((int)threadIdx.x >= o) z += q;
    }
    ws[threadIdx.x] = z;
  }
  __syncthreads();
  int incl = x + (wid ? ws[wid - 1] : 0);
  if (i < NN) g_off[i] = incl - v;
  if (threadIdx.x == 255) g_bsum[blockIdx.x] = incl;
}

__global__ __launch_bounds__(256) void k_scan2() {
  const int NB = (NN + 255) / 256;
  int t = threadIdx.x;
  int v = (t < NB) ? g_bsum[t] : 0;
  int lane = t & 31, wid = t >> 5;
  int x = v;
#pragma unroll
  for (int o = 1; o < 32; o <<= 1) {
    int y = __shfl_up_sync(0xffffffffu, x, o);
    if (lane >= o) x += y;
  }
  __shared__ int ws[8];
  if (lane == 31) ws[wid] = x;
  __syncthreads();
  if (t < 8) {
    int z = ws[t];
#pragma unroll
    for (int o = 1; o < 8; o <<= 1) {
      int q = __shfl_up_sync(0xffu, z, o);
      if (t >= o) z += q;
    }
    ws[t] = z;
  }
  __syncthreads();
  int incl = x + (wid ? ws[wid - 1] : 0);
  if (t < NB) g_bsum[t] = incl - v;
}

__global__ void k_scan3() {
  int i = blockIdx.x * blockDim.x + threadIdx.x;
  if (i < NN) {
    int o = g_off[i] + g_bsum[i >> 8];
    g_off[i] = o;
    g_psrc[o] = i;
    g_cur[i] = o + 1;
  }
  if (i == 0) g_off[NN] = ET;
}

__global__ void k_scatter(const int* __restrict__ ei) {
  int e = blockIdx.x * blockDim.x + threadIdx.x;
  if (e < EE) {
    int s = ei[e];
    int d = ei[EE + e];
    g_psrc[atomicAdd(&g_cur[d], 1)] = s;
  }
}

// ---------------- fp32 -> bf16 hi/lo conversions -------------------------------
__global__ void k_cvt_x(const float* __restrict__ x) {
  int i = blockIdx.x * blockDim.x + threadIdx.x;
  const int n4 = NN * 128 / 4;
  if (i >= n4) return;
  float4 v = __ldg((const float4*)x + i);
  float vv[4] = {v.x, v.y, v.z, v.w};
  __nv_bfloat16 h[4], l[4];
#pragma unroll
  for (int q = 0; q < 4; q++) {
    h[q] = __float2bfloat16(vv[q]);
    l[q] = __float2bfloat16(vv[q] - __bfloat162float(h[q]));
  }
  ((__nv_bfloat162*)g_xhi)[2 * i]     = __nv_bfloat162(h[0], h[1]);
  ((__nv_bfloat162*)g_xhi)[2 * i + 1] = __nv_bfloat162(h[2], h[3]);
  ((__nv_bfloat162*)g_xlo)[2 * i]     = __nv_bfloat162(l[0], l[1]);
  ((__nv_bfloat162*)g_xlo)[2 * i + 1] = __nv_bfloat162(l[2], l[3]);
}

__global__ void k_cvt_w(const float* __restrict__ W1,
                        const float* __restrict__ W2) {
  int i = blockIdx.x * blockDim.x + threadIdx.x;
  if (i < 128 * 256) {
    float v = __ldg(&W1[i]);
    __nv_bfloat16 h = __float2bfloat16(v);
    g_w1hi[i] = h;
    g_w1lo[i] = __float2bfloat16(v - __bfloat162float(h));
  }
  if (i < 256 * 64) {
    float v = __ldg(&W2[i]);
    __nv_bfloat16 h = __float2bfloat16(v);
    g_w2hi[i] = h;
    g_w2lo[i] = __float2bfloat16(v - __bfloat162float(h));
  }
}

// ---------------- wmma GEMM + fused attention-logit epilogue -------------------
// MODE 1: g_h1 = x @ W1, g_als1/g_ald1 (K=128, BN=128, grid.y=2 -> heads 2y,2y+1)
// MODE 2: g_h2lin = h2 @ W2, g_als2/g_ald2 (K=256, BN=64)
template <int MODE>
__global__ __launch_bounds__(256) void k_wgemm(const float* __restrict__ avs,
                                               const float* __restrict__ avd) {
  constexpr int K  = (MODE == 1) ? 128 : 256;
  constexpr int NC = (MODE == 1) ? 256 : 64;
  constexpr int BN = (MODE == 1) ? 128 : 64;
  constexpr int BM = 128, BK = 32;
  constexpr int KT = K / BK;
  constexpr int LDA = 48;
  constexpr int LDB = BN + 16;
  constexpr int NJ = BN / 32;
  constexpr int ASTG = BM * LDA;
  constexpr int BSTG = BK * LDB;
  constexpr int LDC = BN + 4;      // padded fp32 C tile in smem

  extern __shared__ __nv_bfloat16 sm[];
  __nv_bfloat16* Ah = sm;
  __nv_bfloat16* Al = Ah + 2 * ASTG;
  __nv_bfloat16* Bh = Al + 2 * ASTG;
  __nv_bfloat16* Bl = Bh + 2 * BSTG;
  float* Ct = (float*)sm;          // overlay: valid after last MMA

  const __nv_bfloat16* Ahi = (MODE == 1) ? g_xhi : g_h2hi;
  const __nv_bfloat16* Alo = (MODE == 1) ? g_xlo : g_h2lo;
  const __nv_bfloat16* Bhi = (MODE == 1) ? g_w1hi : g_w2hi;
  const __nv_bfloat16* Blo = (MODE == 1) ? g_w1lo : g_w2lo;
  float* C = (MODE == 1) ? g_h1 : g_h2lin;

  const int tid = threadIdx.x;
  const int wid = tid >> 5;
  const int lane = tid & 31;
  const int wr = wid >> 1, wc = wid & 1;
  const int bm = blockIdx.x * BM;
  const int bn = blockIdx.y * BN;

  auto loadA = [&](int kt, int st) {
#pragma unroll
    for (int it = 0; it < 2; it++) {
      int v = it * 256 + tid;
      int r = v >> 2, c8 = (v & 3) << 3;
      int gr = bm + r;
      bool ok = gr < NN;
      size_t go = (size_t)(ok ? gr : 0) * K + kt * BK + c8;
      int so = st * ASTG + r * LDA + c8;
      cp16z((uint32_t)__cvta_generic_to_shared(&Ah[so]), Ahi + go, ok);
      cp16z((uint32_t)__cvta_generic_to_shared(&Al[so]), Alo + go, ok);
    }
  };
  auto loadB = [&](int kt, int st) {
    constexpr int NV = BK * BN / 8;
#pragma unroll
    for (int it = 0; it < NV / 256; it++) {
      int v = it * 256 + tid;
      int r = v / (BN / 8), c8 = (v % (BN / 8)) << 3;
      size_t go = (size_t)(kt * BK + r) * NC + bn + c8;
      int so = st * BSTG + r * LDB + c8;
      cp16z((uint32_t)__cvta_generic_to_shared(&Bh[so]), Bhi + go, true);
      cp16z((uint32_t)__cvta_generic_to_shared(&Bl[so]), Blo + go, true);
    }
  };

  wmma::fragment<wmma::accumulator, 16, 16, 16, float> acc[2][NJ];
#pragma unroll
  for (int i = 0; i < 2; i++)
#pragma unroll
    for (int j = 0; j < NJ; j++) wmma::fill_fragment(acc[i][j], 0.f);

  loadA(0, 0); loadB(0, 0); cpa_commit();

#pragma unroll
  for (int kt = 0; kt < KT; kt++) {
    const int cur = kt & 1;
    if (kt + 1 < KT) { loadA(kt + 1, cur ^ 1); loadB(kt + 1, cur ^ 1); cpa_commit(); }
    if (kt + 1 < KT) cpa_wait<1>(); else cpa_wait<0>();
    __syncthreads();
#pragma unroll
    for (int kk = 0; kk < BK; kk += 16) {
      wmma::fragment<wmma::matrix_a, 16, 16, 16, __nv_bfloat16, wmma::row_major> fah[2], fal[2];
      wmma::fragment<wmma::matrix_b, 16, 16, 16, __nv_bfloat16, wmma::row_major> fbh[NJ], fbl[NJ];
#pragma unroll
      for (int i = 0; i < 2; i++) {
        wmma::load_matrix_sync(fah[i], &Ah[cur * ASTG + (wr * 32 + i * 16) * LDA + kk], LDA);
        wmma::load_matrix_sync(fal[i], &Al[cur * ASTG + (wr * 32 + i * 16) * LDA + kk], LDA);
      }
#pragma unroll
      for (int j = 0; j < NJ; j++) {
        wmma::load_matrix_sync(fbh[j], &Bh[cur * BSTG + kk * LDB + wc * NJ * 16 + j * 16], LDB);
        wmma::load_matrix_sync(fbl[j], &Bl[cur * BSTG + kk * LDB + wc * NJ * 16 + j * 16], LDB);
      }
#pragma unroll
      for (int i = 0; i < 2; i++)
#pragma unroll
        for (int j = 0; j < NJ; j++) {
          wmma::mma_sync(acc[i][j], fah[i], fbh[j], acc[i][j]);
          wmma::mma_sync(acc[i][j], fah[i], fbl[j], acc[i][j]);
          wmma::mma_sync(acc[i][j], fal[i], fbh[j], acc[i][j]);
        }
    }
    __syncthreads();
  }

  // ---- epilogue: stage C tile in smem (pipeline buffers are dead now) ----
#pragma unroll
  for (int i = 0; i < 2; i++)
#pragma unroll
    for (int j = 0; j < NJ; j++)
      wmma::store_matrix_sync(&Ct[(wr * 32 + i * 16) * LDC + wc * NJ * 16 + j * 16],
                              acc[i][j], LDC, wmma::mem_row_major);
  __syncthreads();

  // coalesced copy smem -> gmem
  {
    constexpr int NV4 = BM * BN / 4;
    for (int v = tid; v < NV4; v += 256) {
      int r = v / (BN / 4), c4 = (v % (BN / 4)) << 2;
      if (bm + r < NN)
        *(float4*)&C[(size_t)(bm + r) * NC + bn + c4] = *(float4*)&Ct[r * LDC + c4];
    }
  }

  // fused attention-logit dots
  const int rl = wid * 16 + (lane >> 1);
  const int hl = lane & 1;
  const int row = bm + rl;
  if constexpr (MODE == 1) {
    if (row < NN) {
      const float* cr = &Ct[rl * LDC + hl * 64];
      const float* va = avs + (blockIdx.y * 2 + hl) * 64;
      const float* vd = avd + (blockIdx.y * 2 + hl) * 64;
      float ss = 0.f, dd = 0.f;
#pragma unroll
      for (int t = 0; t < 64; t += 4) {
        float4 c = *(const float4*)(cr + t);
        float4 a = __ldg((const float4*)(va + t));
        float4 d = __ldg((const float4*)(vd + t));
        ss += c.x * a.x + c.y * a.y + c.z * a.z + c.w * a.w;
        dd += c.x * d.x + c.y * d.y + c.z * d.z + c.w * d.w;
      }
      g_als1[row * 4 + blockIdx.y * 2 + hl] = ss;
      g_ald1[row * 4 + blockIdx.y * 2 + hl] = dd;
    }
  } else {
    const float* cr = &Ct[rl * LDC + hl * 32];
    float ss = 0.f, dd = 0.f;
#pragma unroll
    for (int t = 0; t < 32; t += 4) {
      float4 c = *(const float4*)(cr + t);
      float4 a = __ldg((const float4*)(avs + hl * 32 + t));
      float4 d = __ldg((const float4*)(avd + hl * 32 + t));
      ss += c.x * a.x + c.y * a.y + c.z * a.z + c.w * a.w;
      dd += c.x * d.x + c.y * d.y + c.z * d.z + c.w * d.w;
    }
    ss += __shfl_xor_sync(0xffffffffu, ss, 1);
    dd += __shfl_xor_sync(0xffffffffu, dd, 1);
    if (hl == 0 && row < NN) {
      g_als2[row] = ss;
      g_ald2[row] = dd;
    }
  }
}

// ---------------- layer1 aggregation: warp per dst node ----------------------
__global__ __launch_bounds__(256) void k_agg1(const float* __restrict__ b1) {
  int w = (blockIdx.x * 256 + threadIdx.x) >> 5;
  int lane = threadIdx.x & 31;
  if (w >= NN) return;
  const int node = w;
  const int off = g_off[node], end = g_off[node + 1];
  float4 ad = *(const float4*)&g_ald1[node * 4];

  // single-pass online softmax stats
  float m0 = -3e38f, m1 = -3e38f, m2 = -3e38f, m3 = -3e38f;
  float s0 = 0.f, s1 = 0.f, s2 = 0.f, s3 = 0.f;
  for (int j = off + lane; j < end; j += 32) {
    int s = g_psrc[j];
    float4 as = __ldg((const float4*)&g_als1[s * 4]);
    float e0 = lrelu(as.x + ad.x), e1 = lrelu(as.y + ad.y);
    float e2 = lrelu(as.z + ad.z), e3 = lrelu(as.w + ad.w);
    float n0 = fmaxf(m0, e0), n1 = fmaxf(m1, e1);
    float n2 = fmaxf(m2, e2), n3 = fmaxf(m3, e3);
    s0 = s0 * __expf(m0 - n0) + __expf(e0 - n0); m0 = n0;
    s1 = s1 * __expf(m1 - n1) + __expf(e1 - n1); m1 = n1;
    s2 = s2 * __expf(m2 - n2) + __expf(e2 - n2); m2 = n2;
    s3 = s3 * __expf(m3 - n3) + __expf(e3 - n3); m3 = n3;
  }
#pragma unroll
  for (int o = 16; o; o >>= 1) {
    float om, os, nm;
    om = __shfl_xor_sync(0xffffffffu, m0, o); os = __shfl_xor_sync(0xffffffffu, s0, o);
    nm = fmaxf(m0, om); s0 = s0 * __expf(m0 - nm) + os * __expf(om - nm); m0 = nm;
    om = __shfl_xor_sync(0xffffffffu, m1, o); os = __shfl_xor_sync(0xffffffffu, s1, o);
    nm = fmaxf(m1, om); s1 = s1 * __expf(m1 - nm) + os * __expf(om - nm); m1 = nm;
    om = __shfl_xor_sync(0xffffffffu, m2, o); os = __shfl_xor_sync(0xffffffffu, s2, o);
    nm = fmaxf(m2, om); s2 = s2 * __expf(m2 - nm) + os * __expf(om - nm); m2 = nm;
    om = __shfl_xor_sync(0xffffffffu, m3, o); os = __shfl_xor_sync(0xffffffffu, s3, o);
    nm = fmaxf(m3, om); s3 = s3 * __expf(m3 - nm) + os * __expf(om - nm); m3 = nm;
  }
  const int hd = lane >> 3;
  float mh = hd == 0 ? m0 : hd == 1 ? m1 : hd == 2 ? m2 : m3;
  float sh = hd == 0 ? s0 : hd == 1 ? s1 : hd == 2 ? s2 : s3;
  float adh = hd == 0 ? ad.x : hd == 1 ? ad.y : hd == 2 ? ad.z : ad.w;
  float inv = 1.f / (sh + 1e-16f);

  float acc[8] = {0.f, 0.f, 0.f, 0.f, 0.f, 0.f, 0.f, 0.f};
  const int myc = lane << 3;
  int j = off;
  for (; j + 2 <= end; j += 2) {
    int sA = g_psrc[j], sB = g_psrc[j + 1];
    float aA = __ldg(&g_als1[sA * 4 + hd]);
    float aB = __ldg(&g_als1[sB * 4 + hd]);
    const float4* hA = (const float4*)(g_h1 + (size_t)sA * C1 + myc);
    const float4* hB = (const float4*)(g_h1 + (size_t)sB * C1 + myc);
    float4 p0 = __ldg(hA), q0 = __ldg(hA + 1);
    float4 p1 = __ldg(hB), q1 = __ldg(hB + 1);
    float alA = __expf(lrelu(aA + adh) - mh) * inv;
    float alB = __expf(lrelu(aB + adh) - mh) * inv;
    acc[0] += p0.x * alA; acc[1] += p0.y * alA;
    acc[2] += p0.z * alA; acc[3] += p0.w * alA;
    acc[4] += q0.x * alA; acc[5] += q0.y * alA;
    acc[6] += q0.z * alA; acc[7] += q0.w * alA;
    acc[0] += p1.x * alB; acc[1] += p1.y * alB;
    acc[2] += p1.z * alB; acc[3] += p1.w * alB;
    acc[4] += q1.x * alB; acc[5] += q1.y * alB;
    acc[6] += q1.z * alB; acc[7] += q1.w * alB;
  }
  if (j < end) {
    int s = g_psrc[j];
    float asv = __ldg(&g_als1[s * 4 + hd]);
    float alpha = __expf(lrelu(asv + adh) - mh) * inv;
    const float4* hp = (const float4*)(g_h1 + (size_t)s * C1 + myc);
    float4 p = __ldg(hp), q = __ldg(hp + 1);
    acc[0] += p.x * alpha; acc[1] += p.y * alpha;
    acc[2] += p.z * alpha; acc[3] += p.w * alpha;
    acc[4] += q.x * alpha; acc[5] += q.y * alpha;
    acc[6] += q.z * alpha; acc[7] += q.w * alpha;
  }
  float4 bb0 = __ldg((const float4*)&b1[myc]);
  float4 bb1 = __ldg((const float4*)&b1[myc + 4]);
  float vo[8];
  vo[0] = elu_f(acc[0] + bb0.x); vo[1] = elu_f(acc[1] + bb0.y);
  vo[2] = elu_f(acc[2] + bb0.z); vo[3] = elu_f(acc[3] + bb0.w);
  vo[4] = elu_f(acc[4] + bb1.x); vo[5] = elu_f(acc[5] + bb1.y);
  vo[6] = elu_f(acc[6] + bb1.z); vo[7] = elu_f(acc[7] + bb1.w);
  union Pk { __nv_bfloat16 h[8]; uint4 u; } ph, pl;
#pragma unroll
  for (int e = 0; e < 8; e++) {
    ph.h[e] = __float2bfloat16(vo[e]);
    pl.h[e] = __float2bfloat16(vo[e] - __bfloat162float(ph.h[e]));
  }
  *(uint4*)&g_h2hi[(size_t)node * C1 + myc] = ph.u;
  *(uint4*)&g_h2lo[(size_t)node * C1 + myc] = pl.u;
}

// ---------------- layer2 aggregation: warp per dst node ----------------------
__global__ __launch_bounds__(256) void k_agg2(const float* __restrict__ b2,
                                              float* __restrict__ out) {
  int w = (blockIdx.x * 256 + threadIdx.x) >> 5;
  int lane = threadIdx.x & 31;
  if (w >= NN) return;
  const int node = w;
  const int off = g_off[node], end = g_off[node + 1];
  float ad = g_ald2[node];

  float m = -3e38f, su = 0.f;
  for (int j = off + lane; j < end; j += 32) {
    int s = g_psrc[j];
    float e = lrelu(__ldg(&g_als2[s]) + ad);
    float nm = fmaxf(m, e);
    su = su * __expf(m - nm) + __expf(e - nm); m = nm;
  }
#pragma unroll
  for (int o = 16; o; o >>= 1) {
    float om = __shfl_xor_sync(0xffffffffu, m, o);
    float os = __shfl_xor_sync(0xffffffffu, su, o);
    float nm = fmaxf(m, om);
    su = su * __expf(m - nm) + os * __expf(om - nm); m = nm;
  }
  float inv = 1.f / (su + 1e-16f);

  float a0 = 0.f, a1 = 0.f;
  const int c = lane << 1;
  int j = off;
  for (; j + 2 <= end; j += 2) {
    int sA = g_psrc[j], sB = g_psrc[j + 1];
    float eA = __ldg(&g_als2[sA]), eB = __ldg(&g_als2[sB]);
    float2 pA = __ldg((const float2*)(g_h2lin + (size_t)sA * C2 + c));
    float2 pB = __ldg((const float2*)(g_h2lin + (size_t)sB * C2 + c));
    float alA = __expf(lrelu(eA + ad) - m) * inv;
    float alB = __expf(lrelu(eB + ad) - m) * inv;
    a0 += pA.x * alA + pB.x * alB;
    a1 += pA.y * alA + pB.y * alB;
  }
  if (j < end) {
    int s = g_psrc[j];
    float alpha = __expf(lrelu(__ldg(&g_als2[s]) + ad) - m) * inv;
    float2 p = __ldg((const float2*)(g_h2lin + (size_t)s * C2 + c));
    a0 += p.x * alpha;
    a1 += p.y * alpha;
  }
  float2 r;
  r.x = elu_f(a0 + __ldg(&b2[c]));
  r.y = elu_f(a1 + __ldg(&b2[c + 1]));
  *(float2*)(out + (size_t)node * C2 + c) = r;
}

// ---------------- launch ------------------------------------------------------
extern "C" void kernel_launch(void* const* d_in, const int* in_sizes, int n_in,
                              void* d_out, int out_size) {
  const float* x = (const float*)d_in[0];
  const int* ei = (const int*)d_in[1];
  const float* W1 = (const float*)d_in[2];
  const float* as1 = (const float*)d_in[3];
  const float* ad1 = (const float*)d_in[4];
  const float* b1 = (const float*)d_in[5];
  const float* W2 = (const float*)d_in[6];
  const float* as2 = (const float*)d_in[7];
  const float* ad2 = (const float*)d_in[8];
  const float* b2 = (const float*)d_in[9];
  float* out = (float*)d_out;

  static cudaStream_t s_csr = nullptr;
  static cudaEvent_t ev_fork = nullptr, ev_join = nullptr;
  if (!s_csr) {
    cudaStreamCreateWithFlags(&s_csr, cudaStreamNonBlocking);
    cudaEventCreateWithFlags(&ev_fork, cudaEventDisableTiming);
    cudaEventCreateWithFlags(&ev_join, cudaEventDisableTiming);
  }

  const int SMEM1 = (2 * 128 * 48 * 2 + 2 * 32 * (128 + 16) * 2) * 2;  // 86016 B
  const int SMEM2 = (2 * 128 * 48 * 2 + 2 * 32 * (64 + 16) * 2) * 2;   // 69632 B
  cudaFuncSetAttribute(k_wgemm<1>, cudaFuncAttributeMaxDynamicSharedMemorySize, SMEM1);
  cudaFuncSetAttribute(k_wgemm<2>, cudaFuncAttributeMaxDynamicSharedMemorySize, SMEM2);

  const int NB = (NN + 255) / 256;  // 196
  const int NT = (NN + 127) / 128;  // 391

  // fork: CSR chain on side stream, overlapped with cvt+gemm1
  cudaEventRecord(ev_fork, 0);
  cudaStreamWaitEvent(s_csr, ev_fork, 0);
  k_hist<<<(EE + 255) / 256, 256, 0, s_csr>>>(ei);
  k_scan1<<<NB, 256, 0, s_csr>>>();
  k_scan2<<<1, 256, 0, s_csr>>>();
  k_scan3<<<NB, 256, 0, s_csr>>>();
  k_scatter<<<(EE + 255) / 256, 256, 0, s_csr>>>(ei);
  cudaEventRecord(ev_join, s_csr);

  // main chain
  k_cvt_x<<<(NN * 128 / 4 + 255) / 256, 256>>>(x);
  k_cvt_w<<<(128 * 256 + 255) / 256, 256>>>(W1, W2);
  dim3 g1(NT, C1 / 128);
  k_wgemm<1><<<g1, 256, SMEM1>>>(as1, ad1);

  // join: aggregation needs CSR
  cudaStreamWaitEvent(0, ev_join, 0);
  int nwb = (NN * 32 + 255) / 256;
  k_agg1<<<nwb, 256>>>(b1);

  // layer 2
  k_wgemm<2><<<NT, 256, SMEM2>>>(as2, ad2);
  k_agg2<<<nwb, 256>>>(b2, out);
}